// round 6
// baseline (speedup 1.0000x reference)
#include <cuda_runtime.h>
#include <cstdint>

// Problem constants (from reference)
#define N1V   192
#define N2V   48
#define DINV  1024
#define DP1V  1025
#define DOUTV 512
#define LAMV  0.001f
#define LRV   0.01f
#define ITERS 100

// Partitioning: 48 clusters of 6 CTAs; each CTA owns 32 columns of its group's W.
// 512 threads = 16 warps; each warp owns 2 columns; lane l owns rows {j*32+l},
// j=0..31 (rows 0..1023), lane 0 additionally owns bias row 1024.
#define CLUSTER   6
#define COLS_CTA  32
#define THREADS   512
#define WSTRIDE   ((size_t)DP1V * N1V)   // 196800 floats per group matrix

__device__ __forceinline__ float wred(float v) {
    v += __shfl_xor_sync(0xffffffffu, v, 16);
    v += __shfl_xor_sync(0xffffffffu, v, 8);
    v += __shfl_xor_sync(0xffffffffu, v, 4);
    v += __shfl_xor_sync(0xffffffffu, v, 2);
    v += __shfl_xor_sync(0xffffffffu, v, 1);
    return v;
}

// Scalar allreduce across the 6-CTA cluster.
// Caller must have: red[0..15] filled with per-warp partials, and a __syncthreads
// already executed. Warp 0 reduces the CTA partial and thread 0 stores it into
// slot[par][myrank] of EVERY cluster CTA via mapa + st.shared::cluster.
// barrier.cluster (release/acquire) makes the stores visible; then each thread
// sums the 6 local slots. Slots are double-buffered by `par`: the re-write of a
// parity slot at iteration t+2 is ordered after everyone's read at t by the
// intervening barrier at t+1 — one cluster barrier per iteration is enough.
__device__ __forceinline__ float cluster_scalar_allreduce(
    int par, uint32_t rank, int lane, int wid,
    volatile float* red, float (*allslots)[8])
{
    if (wid == 0) {
        float v = (lane < 16) ? red[lane] : 0.0f;
        v = wred(v);
        if (lane == 0) {
            uint32_t la = (uint32_t)__cvta_generic_to_shared(&allslots[par][rank]);
            #pragma unroll
            for (int rk = 0; rk < CLUSTER; ++rk) {
                uint32_t ra;
                asm volatile("mapa.shared::cluster.u32 %0, %1, %2;"
                             : "=r"(ra) : "r"(la), "r"((uint32_t)rk));
                asm volatile("st.shared::cluster.f32 [%0], %1;"
                             :: "r"(ra), "f"(v) : "memory");
            }
        }
    }
    asm volatile("barrier.cluster.arrive.aligned;" ::: "memory");
    asm volatile("barrier.cluster.wait.aligned;"   ::: "memory");
    float s = 0.0f;
    #pragma unroll
    for (int rk = 0; rk < CLUSTER; ++rk) s += allslots[par][rk];
    return s;
}

__global__ void __launch_bounds__(THREADS, 1) __cluster_dims__(CLUSTER, 1, 1)
bls_main(const float* __restrict__ x,
         const float* __restrict__ We,
         const float* __restrict__ W0,
         float* __restrict__ outW)
{
    __shared__ float h1s[DP1V];          // h1 = [x, 1]
    __shared__ float stage[128 * 33];    // 128-row x 32-col staging tile (padded)
    __shared__ float red[16];            // per-warp partials for CTA reduce
    __shared__ float allslots[2][8];     // cluster allreduce slots, double-buffered

    const int tid  = threadIdx.x;
    const int lane = tid & 31;
    const int wid  = tid >> 5;
    const int grp  = blockIdx.x / CLUSTER;
    uint32_t rank;
    asm("mov.u32 %0, %%cluster_ctarank;" : "=r"(rank));
    const int col0 = (int)rank * COLS_CTA;   // first global column of this CTA
    const int wc   = wid * 2;                // warp's local column (0..30)
    const int gc   = col0 + wc;              // warp's global column

    // ---- h1 into smem ----
    h1s[tid]       = x[tid];
    h1s[tid + 512] = x[tid + 512];
    if (tid == 0) h1s[1024] = 1.0f;
    __syncthreads();

    // ---- A_k = h1 . We[grp][:,k], then normalize over the full 192-row ----
    const float* Wep = We + (size_t)grp * WSTRIDE;
    float a0 = 0.0f, a1 = 0.0f;
    for (int c = 0; c < 8; ++c) {
        const float* src = Wep + (size_t)(c * 128) * N1V + col0;
        #pragma unroll
        for (int i = 0; i < 8; ++i) {            // coalesced 128B-per-warp loads
            int idx = tid + i * 512;
            int row = idx >> 5, colz = idx & 31;
            stage[row * 33 + colz] = src[(size_t)row * N1V + colz];
        }
        __syncthreads();
        #pragma unroll
        for (int jj = 0; jj < 4; ++jj) {         // conflict-free (stride-33) reads
            int rl = jj * 32 + lane;
            float h = h1s[c * 128 + rl];
            a0 = fmaf(h, stage[rl * 33 + wc],     a0);
            a1 = fmaf(h, stage[rl * 33 + wc + 1], a1);
        }
        __syncthreads();
    }
    if (lane == 0) {   // bias row, h1[1024] = 1
        a0 += Wep[(size_t)1024 * N1V + gc];
        a1 += Wep[(size_t)1024 * N1V + gc + 1];
    }
    a0 = wred(a0); a1 = wred(a1);                // all lanes hold the dots
    if (lane == 0) red[wid] = a0 * a0 + a1 * a1;
    __syncthreads();
    {
        float atot = cluster_scalar_allreduce(0, rank, lane, wid, red, allslots);
        float ainv = rsqrtf(atot);
        a0 *= ainv; a1 *= ainv;
    }

    // ---- Load W0 into registers; fused first dot / norm^2 pass ----
    const float* W0p = W0 + (size_t)grp * WSTRIDE;
    float w[32][2];
    float wb0 = 0.0f, wb1 = 0.0f;
    float acc0 = 0.0f, acc1 = 0.0f, nacc = 0.0f;
    #pragma unroll
    for (int c = 0; c < 8; ++c) {
        const float* src = W0p + (size_t)(c * 128) * N1V + col0;
        #pragma unroll
        for (int i = 0; i < 8; ++i) {
            int idx = tid + i * 512;
            int row = idx >> 5, colz = idx & 31;
            stage[row * 33 + colz] = src[(size_t)row * N1V + colz];
        }
        __syncthreads();
        #pragma unroll
        for (int jj = 0; jj < 4; ++jj) {
            int j  = c * 4 + jj;
            int rl = jj * 32 + lane;
            float h  = h1s[c * 128 + rl];
            float v0 = stage[rl * 33 + wc];
            float v1 = stage[rl * 33 + wc + 1];
            w[j][0] = v0; w[j][1] = v1;
            acc0 = fmaf(h, v0, acc0);
            acc1 = fmaf(h, v1, acc1);
            nacc = fmaf(v0, v0, fmaf(v1, v1, nacc));
        }
        __syncthreads();
    }
    if (lane == 0) {
        wb0 = W0p[(size_t)1024 * N1V + gc];
        wb1 = W0p[(size_t)1024 * N1V + gc + 1];
        acc0 += wb0; acc1 += wb1;
        nacc = fmaf(wb0, wb0, fmaf(wb1, wb1, nacc));
    }

    // ---- 100 GD iterations ----
    // W <- W*(1 - LR*LAM/||W||) - (2*LR*h1[d])*r[k]; the update pass also
    // accumulates next iteration's dot and ||W||^2 (single sweep over W).
    int par = 1;   // slot 0 was used by the A-normalization exchange
    for (int t = 0; t < ITERS; ++t) {
        float d0 = wred(acc0), d1 = wred(acc1);
        float r0 = d0 - a0, r1 = d1 - a1;
        float tk0 = -2.0f * LRV * r0;
        float tk1 = -2.0f * LRV * r1;

        float nw = wred(nacc);
        if (lane == 0) red[wid] = nw;
        __syncthreads();
        float nsq = cluster_scalar_allreduce(par, rank, lane, wid, red, allslots);
        par ^= 1;
        float s = 1.0f - LRV * LAMV * rsqrtf(nsq);

        acc0 = 0.0f; acc1 = 0.0f; nacc = 0.0f;
        #pragma unroll
        for (int j = 0; j < 32; ++j) {
            float h   = h1s[j * 32 + lane];        // conflict-free broadcast pattern
            float nv0 = fmaf(w[j][0], s, h * tk0);
            float nv1 = fmaf(w[j][1], s, h * tk1);
            w[j][0] = nv0; w[j][1] = nv1;
            acc0 = fmaf(h, nv0, acc0);
            acc1 = fmaf(h, nv1, acc1);
            nacc = fmaf(nv0, nv0, fmaf(nv1, nv1, nacc));
        }
        if (lane == 0) {                           // bias row (h1 = 1)
            wb0 = fmaf(wb0, s, tk0);
            wb1 = fmaf(wb1, s, tk1);
            acc0 += wb0; acc1 += wb1;
            nacc = fmaf(wb0, wb0, fmaf(wb1, wb1, nacc));
        }
    }

    // ---- Store W back (registers -> smem tile -> coalesced global) ----
    float* outp = outW + (size_t)grp * WSTRIDE;
    #pragma unroll
    for (int c = 0; c < 8; ++c) {
        #pragma unroll
        for (int jj = 0; jj < 4; ++jj) {
            int j  = c * 4 + jj;
            int rl = jj * 32 + lane;
            stage[rl * 33 + wc]     = w[j][0];
            stage[rl * 33 + wc + 1] = w[j][1];
        }
        __syncthreads();
        float* dst = outp + (size_t)(c * 128) * N1V + col0;
        #pragma unroll
        for (int i = 0; i < 8; ++i) {
            int idx = tid + i * 512;
            int row = idx >> 5, colz = idx & 31;
            dst[(size_t)row * N1V + colz] = stage[row * 33 + colz];
        }
        __syncthreads();
    }
    if (lane == 0) {
        outp[(size_t)1024 * N1V + gc]     = wb0;
        outp[(size_t)1024 * N1V + gc + 1] = wb1;
    }
}

// pred = x @ Wp^T + bp  (512 outputs; one warp per output; coalesced rows)
__global__ void __launch_bounds__(256)
bls_pred(const float* __restrict__ x, const float* __restrict__ Wp,
         const float* __restrict__ bp, float* __restrict__ out)
{
    int o    = blockIdx.x * 8 + (threadIdx.x >> 5);
    int lane = threadIdx.x & 31;
    const float* row = Wp + (size_t)o * DINV;
    float s = 0.0f;
    #pragma unroll
    for (int i = 0; i < DINV / 32; ++i)
        s = fmaf(row[lane + i * 32], x[lane + i * 32], s);
    s = wred(s);
    if (lane == 0) out[o] = s + bp[o];
}

extern "C" void kernel_launch(void* const* d_in, const int* in_sizes, int n_in,
                              void* d_out, int out_size)
{
    (void)in_sizes; (void)n_in; (void)out_size;
    const float* x  = (const float*)d_in[0];   // (1024,)
    const float* We = (const float*)d_in[1];   // (48, 1025, 192)
    const float* W0 = (const float*)d_in[2];   // (48, 1025, 192)
    const float* Wp = (const float*)d_in[3];   // (512, 1024)
    const float* bp = (const float*)d_in[4];   // (512,)
    float* out = (float*)d_out;                // [pred(512) | W_all(48*1025*192)]

    bls_pred<<<DOUTV / 8, 256>>>(x, Wp, bp, out);
    bls_main<<<N2V * CLUSTER, THREADS>>>(x, We, W0, out + DOUTV);
}

// round 7
// speedup vs baseline: 7.8617x; 7.8617x over previous
#include <cuda_runtime.h>
#include <cstdint>

// Problem constants (from reference)
#define N1V   192
#define N2V   48
#define DINV  1024
#define DP1V  1025
#define DOUTV 512
#define LAMV  0.001f
#define LRV   0.01f
#define BETAD 0.02      // 2*LR (double literal use)

// Partitioning: 48 clusters of 6 CTAs; each CTA owns 32 columns of its group.
// 512 threads: c8 = tid&7 -> 4-col float4 group, r0 = tid>>3 -> row phase.
#define CLUSTER   6
#define COLS_CTA  32
#define THREADS   512
#define WSTRIDE   ((size_t)DP1V * N1V)   // 196800 floats per group matrix

__device__ __forceinline__ float wred(float v) {
    v += __shfl_xor_sync(0xffffffffu, v, 16);
    v += __shfl_xor_sync(0xffffffffu, v, 8);
    v += __shfl_xor_sync(0xffffffffu, v, 4);
    v += __shfl_xor_sync(0xffffffffu, v, 2);
    v += __shfl_xor_sync(0xffffffffu, v, 1);
    return v;
}

// x^100 via repeated squaring (exact-ish fp64): 100 = 64 + 32 + 4
__device__ __forceinline__ double pow100(double s) {
    double s2 = s * s, s4 = s2 * s2, s8 = s4 * s4;
    double s16 = s8 * s8, s32 = s16 * s16, s64 = s32 * s32;
    return s64 * s32 * s4;
}

// Scalar allreduce across the 6-CTA cluster. Caller: red[0..15] filled with
// per-warp partials, __syncthreads already done. Warp 0 reduces, lane 0 stores
// the CTA partial into slot[par][myrank] of every cluster CTA (mapa +
// st.shared::cluster); barrier.cluster publishes; every thread sums 6 slots.
__device__ __forceinline__ float cluster_scalar_allreduce(
    int par, uint32_t rank, int lane, int wid,
    volatile float* red, float (*allslots)[8])
{
    if (wid == 0) {
        float v = (lane < 16) ? red[lane] : 0.0f;
        v = wred(v);
        if (lane == 0) {
            uint32_t la = (uint32_t)__cvta_generic_to_shared(&allslots[par][rank]);
            #pragma unroll
            for (int rk = 0; rk < CLUSTER; ++rk) {
                uint32_t ra;
                asm volatile("mapa.shared::cluster.u32 %0, %1, %2;"
                             : "=r"(ra) : "r"(la), "r"((uint32_t)rk));
                asm volatile("st.shared::cluster.f32 [%0], %1;"
                             :: "r"(ra), "f"(v) : "memory");
            }
        }
    }
    asm volatile("barrier.cluster.arrive.aligned;" ::: "memory");
    asm volatile("barrier.cluster.wait.aligned;"   ::: "memory");
    float s = 0.0f;
    #pragma unroll
    for (int rk = 0; rk < CLUSTER; ++rk) s += allslots[par][rk];
    return s;
}

__global__ void __launch_bounds__(THREADS, 2) __cluster_dims__(CLUSTER, 1, 1)
bls_main(const float* __restrict__ x,
         const float* __restrict__ We,
         const float* __restrict__ W0,
         float* __restrict__ outW)
{
    __shared__ float  h1s[DP1V];
    __shared__ float  cpart[64][33];     // per-thread column partials (64 row-phases x 32 cols)
    __shared__ float  red[16];
    __shared__ float  allslots[2][8];
    __shared__ float  aS[32];            // normalized A for this CTA's columns
    __shared__ float  CsS[32];           // closed-form h-coefficient per column
    __shared__ float  s100_sh;
    __shared__ double h2_sh;             // ||h||^2 (includes bias +1)

    const int tid  = threadIdx.x;
    const int lane = tid & 31;
    const int wid  = tid >> 5;
    const int grp  = blockIdx.x / CLUSTER;
    uint32_t rank;
    asm("mov.u32 %0, %%cluster_ctarank;" : "=r"(rank));
    const int col0 = (int)rank * COLS_CTA;
    const int c8   = tid & 7;            // float4 column-group 0..7
    const int r0   = tid >> 3;           // row phase 0..63

    // ---- h1 into smem; ||h||^2 ----
    const float x0 = x[tid], x1 = x[tid + 512];
    h1s[tid]       = x0;
    h1s[tid + 512] = x1;
    if (tid == 0) h1s[1024] = 1.0f;
    {
        float hq = wred(x0 * x0 + x1 * x1);
        if (lane == 0) red[wid] = hq;
    }
    __syncthreads();
    if (tid == 0) {
        double s = 1.0;                          // bias contributes 1
        #pragma unroll
        for (int i = 0; i < 16; ++i) s += (double)red[i];
        h2_sh = s;
    }
    // (red reuse below is ordered by the pass-A __syncthreads)

    // ---- Pass A: A_k = h . We[grp][:,k]; cluster-normalize over 192 cols ----
    const float* ebase = We + (size_t)grp * WSTRIDE + (size_t)(col0 + c8 * 4);
    {
        float4 acc = make_float4(0.f, 0.f, 0.f, 0.f);
        #pragma unroll 4
        for (int k = 0; k < 16; ++k) {
            int row = r0 + (k << 6);
            float4 v = *(const float4*)(ebase + (size_t)row * N1V);
            float  h = h1s[row];
            acc.x = fmaf(h, v.x, acc.x);
            acc.y = fmaf(h, v.y, acc.y);
            acc.z = fmaf(h, v.z, acc.z);
            acc.w = fmaf(h, v.w, acc.w);
        }
        if (tid < 8) {                           // bias row (h = 1)
            float4 v = *(const float4*)(ebase + (size_t)1024 * N1V);
            acc.x += v.x; acc.y += v.y; acc.z += v.z; acc.w += v.w;
        }
        cpart[r0][c8 * 4 + 0] = acc.x;
        cpart[r0][c8 * 4 + 1] = acc.y;
        cpart[r0][c8 * 4 + 2] = acc.z;
        cpart[r0][c8 * 4 + 3] = acc.w;
    }
    __syncthreads();
    float Aval = 0.0f, contrib = 0.0f;
    if (tid < 32) {
        double s = 0.0;
        #pragma unroll 8
        for (int r = 0; r < 64; ++r) s += (double)cpart[r][tid];
        Aval = (float)s;
        contrib = Aval * Aval;
    }
    {
        float c2 = wred(contrib);                // warps >=1 contribute 0
        if (lane == 0) red[wid] = c2;
    }
    __syncthreads();
    {
        float atot = cluster_scalar_allreduce(0, rank, lane, wid, red, allslots);
        if (tid < 32) aS[tid] = Aval * rsqrtf(atot);
    }
    // cluster barrier inside allreduce fully synced the CTA -> cpart reusable

    // ---- Pass W0: d0_k = h . w0_k  and  ||W0||_F^2 ----
    const float* wbase = W0 + (size_t)grp * WSTRIDE + (size_t)(col0 + c8 * 4);
    float nrm = 0.0f;
    {
        float4 acc = make_float4(0.f, 0.f, 0.f, 0.f);
        #pragma unroll 4
        for (int k = 0; k < 16; ++k) {
            int row = r0 + (k << 6);
            float4 v = *(const float4*)(wbase + (size_t)row * N1V);
            float  h = h1s[row];
            acc.x = fmaf(h, v.x, acc.x);
            acc.y = fmaf(h, v.y, acc.y);
            acc.z = fmaf(h, v.z, acc.z);
            acc.w = fmaf(h, v.w, acc.w);
            nrm = fmaf(v.x, v.x, nrm);
            nrm = fmaf(v.y, v.y, nrm);
            nrm = fmaf(v.z, v.z, nrm);
            nrm = fmaf(v.w, v.w, nrm);
        }
        if (tid < 8) {                           // bias row
            float4 v = *(const float4*)(wbase + (size_t)1024 * N1V);
            acc.x += v.x; acc.y += v.y; acc.z += v.z; acc.w += v.w;
            nrm = fmaf(v.x, v.x, nrm);
            nrm = fmaf(v.y, v.y, nrm);
            nrm = fmaf(v.z, v.z, nrm);
            nrm = fmaf(v.w, v.w, nrm);
        }
        cpart[r0][c8 * 4 + 0] = acc.x;
        cpart[r0][c8 * 4 + 1] = acc.y;
        cpart[r0][c8 * 4 + 2] = acc.z;
        cpart[r0][c8 * 4 + 3] = acc.w;
    }
    {
        float nw = wred(nrm);
        if (lane == 0) red[wid] = nw;
    }
    __syncthreads();
    float ntot = cluster_scalar_allreduce(1, rank, lane, wid, red, allslots);

    float d0 = 0.0f;
    if (tid < 32) {
        double s = 0.0;
        #pragma unroll 8
        for (int r = 0; r < 64; ++r) s += (double)cpart[r][tid];
        d0 = (float)s;
    }

    // ---- Closed form of 100 GD steps with frozen s = 1 - LR*LAM/||W0|| ----
    // M = sI - beta*h h^T:  w100 = s^100 w0 + [gam*d0 + beta*sig*a] h
    // gam = (mu^100 - s^100)/||h||^2,  mu = s - beta*||h||^2,
    // sig = (1 - mu^100)/(1 - mu).
    __shared__ double gam_sh, bsig_sh;
    if (tid == 0) {
        double nrmW  = sqrt((double)ntot);
        double s     = 1.0 - (double)LRV * (double)LAMV / nrmW;
        double hh    = h2_sh;
        double mu    = s - BETAD * hh;
        double s100  = pow100(s);
        double mu100 = pow100(mu);
        gam_sh  = (mu100 - s100) / hh;
        bsig_sh = BETAD * (1.0 - mu100) / (1.0 - mu);
        s100_sh = (float)s100;
    }
    __syncthreads();
    if (tid < 32)
        CsS[tid] = (float)(gam_sh * (double)d0 + bsig_sh * (double)aS[tid]);
    __syncthreads();

    // ---- Epilogue: w_out = s100 * w0 + C_k * h  (W0 re-read hits L2) ----
    const float s100f = s100_sh;
    const float4 Cv = make_float4(CsS[c8 * 4 + 0], CsS[c8 * 4 + 1],
                                  CsS[c8 * 4 + 2], CsS[c8 * 4 + 3]);
    float* obase = outW + (size_t)grp * WSTRIDE + (size_t)(col0 + c8 * 4);
    #pragma unroll 4
    for (int k = 0; k < 16; ++k) {
        int row = r0 + (k << 6);
        float4 v = *(const float4*)(wbase + (size_t)row * N1V);
        float  h = h1s[row];
        float4 o;
        o.x = fmaf(s100f, v.x, h * Cv.x);
        o.y = fmaf(s100f, v.y, h * Cv.y);
        o.z = fmaf(s100f, v.z, h * Cv.z);
        o.w = fmaf(s100f, v.w, h * Cv.w);
        *(float4*)(obase + (size_t)row * N1V) = o;
    }
    if (tid < 8) {                               // bias row (h = 1)
        float4 v = *(const float4*)(wbase + (size_t)1024 * N1V);
        float4 o;
        o.x = fmaf(s100f, v.x, Cv.x);
        o.y = fmaf(s100f, v.y, Cv.y);
        o.z = fmaf(s100f, v.z, Cv.z);
        o.w = fmaf(s100f, v.w, Cv.w);
        *(float4*)(obase + (size_t)1024 * N1V) = o;
    }
    // No trailing cluster sync needed: last remote DSMEM stores were published
    // by the parity-1 allreduce barrier; peers only touch their own smem after.
}

// pred = x @ Wp^T + bp  (512 outputs; one warp per output; coalesced rows)
__global__ void __launch_bounds__(256)
bls_pred(const float* __restrict__ x, const float* __restrict__ Wp,
         const float* __restrict__ bp, float* __restrict__ out)
{
    int o    = blockIdx.x * 8 + (threadIdx.x >> 5);
    int lane = threadIdx.x & 31;
    const float* row = Wp + (size_t)o * DINV;
    float s = 0.0f;
    #pragma unroll
    for (int i = 0; i < DINV / 32; ++i)
        s = fmaf(row[lane + i * 32], x[lane + i * 32], s);
    s = wred(s);
    if (lane == 0) out[o] = s + bp[o];
}

extern "C" void kernel_launch(void* const* d_in, const int* in_sizes, int n_in,
                              void* d_out, int out_size)
{
    (void)in_sizes; (void)n_in; (void)out_size;
    const float* x  = (const float*)d_in[0];   // (1024,)
    const float* We = (const float*)d_in[1];   // (48, 1025, 192)
    const float* W0 = (const float*)d_in[2];   // (48, 1025, 192)
    const float* Wp = (const float*)d_in[3];   // (512, 1024)
    const float* bp = (const float*)d_in[4];   // (512,)
    float* out = (float*)d_out;                // [pred(512) | W_all(48*1025*192)]

    bls_pred<<<DOUTV / 8, 256>>>(x, Wp, bp, out);
    bls_main<<<N2V * CLUSTER, THREADS>>>(x, We, W0, out + DOUTV);
}

// round 9
// speedup vs baseline: 9.5293x; 1.2121x over previous
#include <cuda_runtime.h>
#include <cstdint>

// Problem constants (from reference)
#define N1V   192
#define N2V   48
#define DINV  1024
#define DP1V  1025
#define DOUTV 512
#define LAMV  0.001f
#define LRV   0.01f
#define BETAD 0.02      // 2*LR (double)

// 48 clusters of 6 CTAs; each CTA owns 32 columns of its group's W.
// 512 threads: c8 = tid&7 -> float4 column group, r0 = tid>>3 -> row phase.
#define CLUSTER   6
#define COLS_CTA  32
#define THREADS   512
#define WSTRIDE   ((size_t)DP1V * N1V)   // 196800 floats per group matrix

__device__ __forceinline__ float wred(float v) {
    v += __shfl_xor_sync(0xffffffffu, v, 16);
    v += __shfl_xor_sync(0xffffffffu, v, 8);
    v += __shfl_xor_sync(0xffffffffu, v, 4);
    v += __shfl_xor_sync(0xffffffffu, v, 2);
    v += __shfl_xor_sync(0xffffffffu, v, 1);
    return v;
}

// x^100 via repeated squaring: 100 = 64 + 32 + 4
__device__ __forceinline__ double pow100(double s) {
    double s2 = s * s, s4 = s2 * s2, s8 = s4 * s4;
    double s16 = s8 * s8, s32 = s16 * s16, s64 = s32 * s32;
    return s64 * s32 * s4;
}

__global__ void __launch_bounds__(THREADS, 2) __cluster_dims__(CLUSTER, 1, 1)
bls_fused(const float* __restrict__ x,
          const float* __restrict__ We,
          const float* __restrict__ W0,
          const float* __restrict__ Wp,
          const float* __restrict__ bp,
          float* __restrict__ out)     // [pred(512) | W_all]
{
    __shared__ float  h1s[DP1V];
    __shared__ float  cpartA[64][33];    // per-thread partials: A = h.We cols
    __shared__ float  cpartD[64][33];    // per-thread partials: d0 = h.W0 cols
    __shared__ float  redA[16], redN[16], redH[16], predp[16];
    __shared__ float  slotsA[8], slotsN[8];   // cluster allreduce slots
    __shared__ float  aS[32];            // per-column A (pre-normalization)
    __shared__ float  dS[32];            // per-column d0
    __shared__ float  CsS[32];           // closed-form h-coefficient per column
    __shared__ float  s100_sh;
    __shared__ double gam_sh, bsig_sh;

    const int tid  = threadIdx.x;
    const int lane = tid & 31;
    const int wid  = tid >> 5;
    const int bid  = blockIdx.x;
    const int grp  = bid / CLUSTER;
    uint32_t rank;
    asm("mov.u32 %0, %%cluster_ctarank;" : "=r"(rank));
    const int col0 = (int)rank * COLS_CTA;
    const int c8   = tid & 7;            // float4 column-group 0..7
    const int r0   = tid >> 3;           // row phase 0..63

    // ---- h1 into smem; per-warp ||x||^2 partials; folded pred dot ----
    const float x0 = x[tid], x1 = x[tid + 512];
    h1s[tid]       = x0;
    h1s[tid + 512] = x1;
    if (tid == 0) h1s[1024] = 1.0f;
    {
        float hq = wred(x0 * x0 + x1 * x1);
        if (lane == 0) redH[wid] = hq;
    }
    // pred: CTAs 0..255 compute out[2*bid] (warps 0-7) and out[2*bid+1] (8-15)
    if (bid < 256) {
        const float* row = Wp + (size_t)(2 * bid + (wid >> 3)) * DINV
                              + (size_t)(wid & 7) * 128 + lane;
        float p = 0.0f;
        #pragma unroll
        for (int i = 0; i < 4; ++i) p = fmaf(row[i * 32], x[(wid & 7) * 128 + lane + i * 32], p);
        p = wred(p);
        if (lane == 0) predp[wid] = p;
    }
    __syncthreads();
    if (bid < 256 && tid < 2) {
        float s = 0.0f;
        #pragma unroll
        for (int i = 0; i < 8; ++i) s += predp[tid * 8 + i];
        out[2 * bid + tid] = s + bp[2 * bid + tid];
    }
    double h2 = 0.0;                     // only tid 0's value is ever used
    if (tid == 0) {
        double s = 1.0;                  // bias row contributes 1
        #pragma unroll
        for (int i = 0; i < 16; ++i) s += (double)redH[i];
        h2 = s;
    }

    // ---- Fused sweep: A_k = h.We[:,k], d0_k = h.W0[:,k], ||W0||^2 ----
    const float* ebase = We + (size_t)grp * WSTRIDE + (size_t)(col0 + c8 * 4);
    const float* wbase = W0 + (size_t)grp * WSTRIDE + (size_t)(col0 + c8 * 4);
    float4 accA = make_float4(0.f, 0.f, 0.f, 0.f);
    float4 accD = make_float4(0.f, 0.f, 0.f, 0.f);
    float  nrm  = 0.0f;
    #pragma unroll
    for (int k = 0; k < 16; ++k) {
        const int row = r0 + (k << 6);
        const size_t off = (size_t)row * N1V;
        float4 e = *(const float4*)(ebase + off);   // independent load streams:
        float4 w = *(const float4*)(wbase + off);   // 2 LDG.128 per iter, 16 iters
        float  h = h1s[row];
        accA.x = fmaf(h, e.x, accA.x);  accA.y = fmaf(h, e.y, accA.y);
        accA.z = fmaf(h, e.z, accA.z);  accA.w = fmaf(h, e.w, accA.w);
        accD.x = fmaf(h, w.x, accD.x);  accD.y = fmaf(h, w.y, accD.y);
        accD.z = fmaf(h, w.z, accD.z);  accD.w = fmaf(h, w.w, accD.w);
        nrm = fmaf(w.x, w.x, nrm);  nrm = fmaf(w.y, w.y, nrm);
        nrm = fmaf(w.z, w.z, nrm);  nrm = fmaf(w.w, w.w, nrm);
    }
    if (tid < 8) {                       // bias row 1024 (h = 1)
        float4 e = *(const float4*)(ebase + (size_t)1024 * N1V);
        float4 w = *(const float4*)(wbase + (size_t)1024 * N1V);
        accA.x += e.x; accA.y += e.y; accA.z += e.z; accA.w += e.w;
        accD.x += w.x; accD.y += w.y; accD.z += w.z; accD.w += w.w;
        nrm = fmaf(w.x, w.x, nrm);  nrm = fmaf(w.y, w.y, nrm);
        nrm = fmaf(w.z, w.z, nrm);  nrm = fmaf(w.w, w.w, nrm);
    }
    cpartA[r0][c8 * 4 + 0] = accA.x;  cpartA[r0][c8 * 4 + 1] = accA.y;
    cpartA[r0][c8 * 4 + 2] = accA.z;  cpartA[r0][c8 * 4 + 3] = accA.w;
    cpartD[r0][c8 * 4 + 0] = accD.x;  cpartD[r0][c8 * 4 + 1] = accD.y;
    cpartD[r0][c8 * 4 + 2] = accD.z;  cpartD[r0][c8 * 4 + 3] = accD.w;
    {
        float nw = wred(nrm);
        if (lane == 0) redN[wid] = nw;
    }
    __syncthreads();

    // ---- Warp-parallel CTA column reduction: warp w owns columns 2w, 2w+1 ----
    // Stride-33 rows -> bank = lane + const (mod 32): conflict-free.
    {
        const int cA = 2 * wid, cB = 2 * wid + 1;
        float a0 = cpartA[lane][cA] + cpartA[lane + 32][cA];
        float a1 = cpartA[lane][cB] + cpartA[lane + 32][cB];
        float d0 = cpartD[lane][cA] + cpartD[lane + 32][cA];
        float d1 = cpartD[lane][cB] + cpartD[lane + 32][cB];
        a0 = wred(a0); a1 = wred(a1); d0 = wred(d0); d1 = wred(d1);
        if (lane == 0) {
            aS[cA] = a0; aS[cB] = a1;
            dS[cA] = d0; dS[cB] = d1;
            redA[wid] = a0 * a0 + a1 * a1;   // local piece of sum-of-A^2
        }
    }
    __syncthreads();

    // ---- ONE combined cluster allreduce: {sum A^2, ||W0||^2} ----
    // Warp 0 reduces redA, warp 1 reduces redN; lane 0 of each stores its
    // scalar into the matching slot of every cluster CTA; one cluster barrier
    // publishes both.
    if (wid < 2) {
        float v = (lane < 16) ? (wid == 0 ? redA[lane] : redN[lane]) : 0.0f;
        v = wred(v);
        if (lane == 0) {
            float* slot = (wid == 0) ? &slotsA[rank] : &slotsN[rank];
            uint32_t la = (uint32_t)__cvta_generic_to_shared(slot);
            #pragma unroll
            for (int rk = 0; rk < CLUSTER; ++rk) {
                uint32_t ra;
                asm volatile("mapa.shared::cluster.u32 %0, %1, %2;"
                             : "=r"(ra) : "r"(la), "r"((uint32_t)rk));
                asm volatile("st.shared::cluster.f32 [%0], %1;"
                             :: "r"(ra), "f"(v) : "memory");
            }
        }
    }
    asm volatile("barrier.cluster.arrive.aligned;" ::: "memory");
    asm volatile("barrier.cluster.wait.aligned;"   ::: "memory");

    // ---- Closed form of 100 GD steps with frozen s = 1 - LR*LAM/||W0|| ----
    // w100 = s^100 w0 + [gam*d0 + beta*sig*(A/||A||)] h
    // gam = (mu^100 - s^100)/||h||^2,  mu = s - beta*||h||^2,
    // sig = (1 - mu^100)/(1 - mu)
    if (tid == 0) {
        float at = 0.0f, nt = 0.0f;
        #pragma unroll
        for (int rk = 0; rk < CLUSTER; ++rk) { at += slotsA[rk]; nt += slotsN[rk]; }
        double s     = 1.0 - (double)LRV * (double)LAMV / sqrt((double)nt);
        double mu    = s - BETAD * h2;
        double s100  = pow100(s);
        double mu100 = pow100(mu);
        gam_sh  = (mu100 - s100) / h2;
        // fold the A-normalization 1/||A|| into the a-coefficient:
        bsig_sh = BETAD * (1.0 - mu100) / (1.0 - mu) / sqrt((double)at);
        s100_sh = (float)s100;
    }
    __syncthreads();
    if (tid < 32)
        CsS[tid] = (float)(gam_sh * (double)dS[tid] + bsig_sh * (double)aS[tid]);
    __syncthreads();

    // ---- Epilogue: w_out = s100 * w0 + C_k * h  (W0 re-read hits L2) ----
    const float s100f = s100_sh;
    const float4 Cv = make_float4(CsS[c8 * 4 + 0], CsS[c8 * 4 + 1],
                                  CsS[c8 * 4 + 2], CsS[c8 * 4 + 3]);
    float* obase = out + DOUTV + (size_t)grp * WSTRIDE + (size_t)(col0 + c8 * 4);
    #pragma unroll
    for (int k = 0; k < 16; ++k) {
        const int row = r0 + (k << 6);
        const size_t off = (size_t)row * N1V;
        float4 v = *(const float4*)(wbase + off);
        float  h = h1s[row];
        float4 o;
        o.x = fmaf(s100f, v.x, h * Cv.x);
        o.y = fmaf(s100f, v.y, h * Cv.y);
        o.z = fmaf(s100f, v.z, h * Cv.z);
        o.w = fmaf(s100f, v.w, h * Cv.w);
        *(float4*)(obase + off) = o;
    }
    if (tid < 8) {                               // bias row (h = 1)
        float4 v = *(const float4*)(wbase + (size_t)1024 * N1V);
        float4 o;
        o.x = fmaf(s100f, v.x, Cv.x);
        o.y = fmaf(s100f, v.y, Cv.y);
        o.z = fmaf(s100f, v.z, Cv.z);
        o.w = fmaf(s100f, v.w, Cv.w);
        *(float4*)(obase + (size_t)1024 * N1V) = o;
    }
    // No trailing cluster sync needed: the remote DSMEM slot stores were
    // published by the single allreduce barrier, and peers only read their
    // own smem afterwards.
}

extern "C" void kernel_launch(void* const* d_in, const int* in_sizes, int n_in,
                              void* d_out, int out_size)
{
    (void)in_sizes; (void)n_in; (void)out_size;
    const float* x  = (const float*)d_in[0];   // (1024,)
    const float* We = (const float*)d_in[1];   // (48, 1025, 192)
    const float* W0 = (const float*)d_in[2];   // (48, 1025, 192)
    const float* Wp = (const float*)d_in[3];   // (512, 1024)
    const float* bp = (const float*)d_in[4];   // (512,)
    float* out = (float*)d_out;                // [pred(512) | W_all]

    bls_fused<<<N2V * CLUSTER, THREADS>>>(x, We, W0, Wp, bp, out);
}

// round 10
// speedup vs baseline: 16.0652x; 1.6859x over previous
#include <cuda_runtime.h>
#include <cstdint>

// Problem constants (from reference)
#define N1V   192
#define N2V   48
#define DINV  1024
#define DP1V  1025
#define DOUTV 512
#define LAMV  0.001f
#define LRV   0.01f
#define BETAD 0.02      // 2*LR (double)

// 48 clusters of 6 CTAs; each CTA owns 32 columns of its group's W.
// 512 threads: c8 = tid&7 -> float4 column group, r0 = tid>>3 -> row phase.
#define CLUSTER   6
#define COLS_CTA  32
#define THREADS   512
#define DEPTH     4                      // cp.async pipeline depth (batches)
#define WSTRIDE   ((size_t)DP1V * N1V)   // 196800 floats per group matrix

struct __align__(16) Smem {
    float4 bufE[DEPTH][THREADS];         // per-thread cp.async slots (We)
    float4 bufW[DEPTH][THREADS];         // per-thread cp.async slots (W0)
    float  h1s[1028];
    float  cpartA[64][33];
    float  cpartD[64][33];
    float  redA[16], redN[16], redH[16], predp[16];
    float  slotsA[8], slotsN[8];
    float  aS[32], dS[32], CsS[32];
    float  s100;
    double gam, bsig;
};

__device__ __forceinline__ float wred(float v) {
    v += __shfl_xor_sync(0xffffffffu, v, 16);
    v += __shfl_xor_sync(0xffffffffu, v, 8);
    v += __shfl_xor_sync(0xffffffffu, v, 4);
    v += __shfl_xor_sync(0xffffffffu, v, 2);
    v += __shfl_xor_sync(0xffffffffu, v, 1);
    return v;
}

// x^100 via repeated squaring: 100 = 64 + 32 + 4
__device__ __forceinline__ double pow100(double s) {
    double s2 = s * s, s4 = s2 * s2, s8 = s4 * s4;
    double s16 = s8 * s8, s32 = s16 * s16, s64 = s32 * s32;
    return s64 * s32 * s4;
}

__device__ __forceinline__ void cpasync16(void* sp, const void* gp) {
    uint32_t sa = (uint32_t)__cvta_generic_to_shared(sp);
    asm volatile("cp.async.cg.shared.global [%0], [%1], 16;"
                 :: "r"(sa), "l"(gp) : "memory");
}
#define CP_COMMIT() asm volatile("cp.async.commit_group;" ::: "memory")
#define CP_WAIT(n)  asm volatile("cp.async.wait_group %0;" :: "n"(n) : "memory")

__global__ void __launch_bounds__(THREADS, 2) __cluster_dims__(CLUSTER, 1, 1)
bls_fused(const float* __restrict__ x,
          const float* __restrict__ We,
          const float* __restrict__ W0,
          const float* __restrict__ Wp,
          const float* __restrict__ bp,
          float* __restrict__ out)     // [pred(512) | W_all]
{
    extern __shared__ Smem sm[];

    const int tid  = threadIdx.x;
    const int lane = tid & 31;
    const int wid  = tid >> 5;
    const int bid  = blockIdx.x;
    const int grp  = bid / CLUSTER;
    uint32_t rank;
    asm("mov.u32 %0, %%cluster_ctarank;" : "=r"(rank));
    const int col0 = (int)rank * COLS_CTA;
    const int c8   = tid & 7;            // float4 column-group 0..7
    const int r0   = tid >> 3;           // row phase 0..63

    const float* ebase = We + (size_t)grp * WSTRIDE + (size_t)(col0 + c8 * 4);
    const float* wbase = W0 + (size_t)grp * WSTRIDE + (size_t)(col0 + c8 * 4);

    // ---- Kick off the sweep pipeline FIRST: DRAM busy from cycle ~0.
    // Per-thread slots: thread t writes and reads only bufE/bufW[*][t], so the
    // pipeline needs only cp.async.wait_group, never __syncthreads.
    #pragma unroll
    for (int b = 0; b < DEPTH; ++b) {
        const size_t off = (size_t)(r0 + (b << 6)) * N1V;
        cpasync16(&sm->bufE[b][tid], ebase + off);
        cpasync16(&sm->bufW[b][tid], wbase + off);
        CP_COMMIT();
    }

    // ---- h1 into smem; per-warp ||x||^2 partials; folded pred dot ----
    const float x0 = x[tid], x1 = x[tid + 512];
    sm->h1s[tid]       = x0;
    sm->h1s[tid + 512] = x1;
    if (tid == 0) sm->h1s[1024] = 1.0f;
    {
        float hq = wred(x0 * x0 + x1 * x1);
        if (lane == 0) sm->redH[wid] = hq;
    }
    // pred: CTAs 0..255 compute out[2*bid] (warps 0-7) and out[2*bid+1] (8-15)
    if (bid < 256) {
        const float* row = Wp + (size_t)(2 * bid + (wid >> 3)) * DINV
                              + (size_t)(wid & 7) * 128 + lane;
        float p = 0.0f;
        #pragma unroll
        for (int i = 0; i < 4; ++i)
            p = fmaf(row[i * 32], x[(wid & 7) * 128 + lane + i * 32], p);
        p = wred(p);
        if (lane == 0) sm->predp[wid] = p;
    }
    __syncthreads();
    if (bid < 256 && tid < 2) {
        float s = 0.0f;
        #pragma unroll
        for (int i = 0; i < 8; ++i) s += sm->predp[tid * 8 + i];
        out[2 * bid + tid] = s + bp[2 * bid + tid];
    }
    double h2 = 0.0;                     // only tid 0's value is ever used
    if (tid == 0) {
        double s = 1.0;                  // bias row contributes 1
        #pragma unroll
        for (int i = 0; i < 16; ++i) s += (double)sm->redH[i];
        h2 = s;
    }

    // ---- Fused pipelined sweep: A_k = h.We[:,k], d0_k = h.W0[:,k], ||W0||^2
    float4 accA = make_float4(0.f, 0.f, 0.f, 0.f);
    float4 accD = make_float4(0.f, 0.f, 0.f, 0.f);
    float  nrm  = 0.0f;
    #pragma unroll
    for (int k = 0; k < 16; ++k) {
        CP_WAIT(DEPTH - 1);                     // batch k complete (in-order)
        float4 e = sm->bufE[k & (DEPTH - 1)][tid];
        float4 w = sm->bufW[k & (DEPTH - 1)][tid];
        float  h = sm->h1s[r0 + (k << 6)];
        if (k + DEPTH < 16) {                   // refill slot we just drained
            const size_t off = (size_t)(r0 + ((k + DEPTH) << 6)) * N1V;
            cpasync16(&sm->bufE[k & (DEPTH - 1)][tid], ebase + off);
            cpasync16(&sm->bufW[k & (DEPTH - 1)][tid], wbase + off);
        }
        CP_COMMIT();                            // 1 group per k (may be empty)
        accA.x = fmaf(h, e.x, accA.x);  accA.y = fmaf(h, e.y, accA.y);
        accA.z = fmaf(h, e.z, accA.z);  accA.w = fmaf(h, e.w, accA.w);
        accD.x = fmaf(h, w.x, accD.x);  accD.y = fmaf(h, w.y, accD.y);
        accD.z = fmaf(h, w.z, accD.z);  accD.w = fmaf(h, w.w, accD.w);
        nrm = fmaf(w.x, w.x, nrm);  nrm = fmaf(w.y, w.y, nrm);
        nrm = fmaf(w.z, w.z, nrm);  nrm = fmaf(w.w, w.w, nrm);
    }
    if (tid < 8) {                       // bias row 1024 (h = 1)
        float4 e = *(const float4*)(ebase + (size_t)1024 * N1V);
        float4 w = *(const float4*)(wbase + (size_t)1024 * N1V);
        accA.x += e.x; accA.y += e.y; accA.z += e.z; accA.w += e.w;
        accD.x += w.x; accD.y += w.y; accD.z += w.z; accD.w += w.w;
        nrm = fmaf(w.x, w.x, nrm);  nrm = fmaf(w.y, w.y, nrm);
        nrm = fmaf(w.z, w.z, nrm);  nrm = fmaf(w.w, w.w, nrm);
    }

    // ---- Prefetch epilogue W0 batches NOW: overlaps reductions + barrier.
    // Slot reuse is safe: thread t already consumed its own sweep slots.
    #pragma unroll
    for (int b = 0; b < DEPTH; ++b) {
        const size_t off = (size_t)(r0 + (b << 6)) * N1V;
        cpasync16(&sm->bufW[b][tid], wbase + off);
        CP_COMMIT();
    }

    sm->cpartA[r0][c8 * 4 + 0] = accA.x;  sm->cpartA[r0][c8 * 4 + 1] = accA.y;
    sm->cpartA[r0][c8 * 4 + 2] = accA.z;  sm->cpartA[r0][c8 * 4 + 3] = accA.w;
    sm->cpartD[r0][c8 * 4 + 0] = accD.x;  sm->cpartD[r0][c8 * 4 + 1] = accD.y;
    sm->cpartD[r0][c8 * 4 + 2] = accD.z;  sm->cpartD[r0][c8 * 4 + 3] = accD.w;
    {
        float nw = wred(nrm);
        if (lane == 0) sm->redN[wid] = nw;
    }
    __syncthreads();

    // ---- Warp-parallel CTA column reduction: warp w owns columns 2w, 2w+1 ----
    {
        const int cA = 2 * wid, cB = 2 * wid + 1;
        float a0 = sm->cpartA[lane][cA] + sm->cpartA[lane + 32][cA];
        float a1 = sm->cpartA[lane][cB] + sm->cpartA[lane + 32][cB];
        float d0 = sm->cpartD[lane][cA] + sm->cpartD[lane + 32][cA];
        float d1 = sm->cpartD[lane][cB] + sm->cpartD[lane + 32][cB];
        a0 = wred(a0); a1 = wred(a1); d0 = wred(d0); d1 = wred(d1);
        if (lane == 0) {
            sm->aS[cA] = a0; sm->aS[cB] = a1;
            sm->dS[cA] = d0; sm->dS[cB] = d1;
            sm->redA[wid] = a0 * a0 + a1 * a1;
        }
    }
    __syncthreads();

    // ---- ONE combined cluster allreduce: {sum A^2, ||W0||^2} ----
    if (wid < 2) {
        float v = (lane < 16) ? (wid == 0 ? sm->redA[lane] : sm->redN[lane]) : 0.0f;
        v = wred(v);
        if (lane == 0) {
            float* slot = (wid == 0) ? &sm->slotsA[rank] : &sm->slotsN[rank];
            uint32_t la = (uint32_t)__cvta_generic_to_shared(slot);
            #pragma unroll
            for (int rk = 0; rk < CLUSTER; ++rk) {
                uint32_t ra;
                asm volatile("mapa.shared::cluster.u32 %0, %1, %2;"
                             : "=r"(ra) : "r"(la), "r"((uint32_t)rk));
                asm volatile("st.shared::cluster.f32 [%0], %1;"
                             :: "r"(ra), "f"(v) : "memory");
            }
        }
    }
    asm volatile("barrier.cluster.arrive.aligned;" ::: "memory");
    asm volatile("barrier.cluster.wait.aligned;"   ::: "memory");

    // ---- Closed form of 100 GD steps with frozen s = 1 - LR*LAM/||W0|| ----
    // w100 = s^100 w0 + [gam*d0 + beta*sig*(A/||A||)] h
    if (tid == 0) {
        float at = 0.0f, nt = 0.0f;
        #pragma unroll
        for (int rk = 0; rk < CLUSTER; ++rk) { at += sm->slotsA[rk]; nt += sm->slotsN[rk]; }
        double s     = 1.0 - (double)LRV * (double)LAMV / sqrt((double)nt);
        double mu    = s - BETAD * h2;
        double s100  = pow100(s);
        double mu100 = pow100(mu);
        sm->gam  = (mu100 - s100) / h2;
        sm->bsig = BETAD * (1.0 - mu100) / (1.0 - mu) / sqrt((double)at);
        sm->s100 = (float)s100;
    }
    __syncthreads();
    if (tid < 32)
        sm->CsS[tid] = (float)(sm->gam * (double)sm->dS[tid]
                             + sm->bsig * (double)sm->aS[tid]);
    __syncthreads();

    // ---- Pipelined epilogue: w_out = s100*w0 + C_k*h; streaming stores ----
    const float s100f = sm->s100;
    const float4 Cv = make_float4(sm->CsS[c8 * 4 + 0], sm->CsS[c8 * 4 + 1],
                                  sm->CsS[c8 * 4 + 2], sm->CsS[c8 * 4 + 3]);
    float* obase = out + DOUTV + (size_t)grp * WSTRIDE + (size_t)(col0 + c8 * 4);
    #pragma unroll
    for (int k = 0; k < 16; ++k) {
        CP_WAIT(DEPTH - 1);
        float4 v = sm->bufW[k & (DEPTH - 1)][tid];
        if (k + DEPTH < 16) {
            const size_t off = (size_t)(r0 + ((k + DEPTH) << 6)) * N1V;
            cpasync16(&sm->bufW[k & (DEPTH - 1)][tid], wbase + off);
        }
        CP_COMMIT();
        const float h = sm->h1s[r0 + (k << 6)];
        float4 o;
        o.x = fmaf(s100f, v.x, h * Cv.x);
        o.y = fmaf(s100f, v.y, h * Cv.y);
        o.z = fmaf(s100f, v.z, h * Cv.z);
        o.w = fmaf(s100f, v.w, h * Cv.w);
        __stcs((float4*)(obase + (size_t)(r0 + (k << 6)) * N1V), o);
    }
    if (tid < 8) {                               // bias row (h = 1)
        float4 v = *(const float4*)(wbase + (size_t)1024 * N1V);
        float4 o;
        o.x = fmaf(s100f, v.x, Cv.x);
        o.y = fmaf(s100f, v.y, Cv.y);
        o.z = fmaf(s100f, v.z, Cv.z);
        o.w = fmaf(s100f, v.w, Cv.w);
        __stcs((float4*)(obase + (size_t)1024 * N1V), o);
    }
    // No trailing cluster sync needed: remote DSMEM slot stores were published
    // by the allreduce barrier; peers only read their own smem afterwards.
}

extern "C" void kernel_launch(void* const* d_in, const int* in_sizes, int n_in,
                              void* d_out, int out_size)
{
    (void)in_sizes; (void)n_in; (void)out_size;
    const float* x  = (const float*)d_in[0];   // (1024,)
    const float* We = (const float*)d_in[1];   // (48, 1025, 192)
    const float* W0 = (const float*)d_in[2];   // (48, 1025, 192)
    const float* Wp = (const float*)d_in[3];   // (512, 1024)
    const float* bp = (const float*)d_in[4];   // (512,)
    float* out = (float*)d_out;                // [pred(512) | W_all]

    static int smem_set = 0;
    if (!smem_set) {
        cudaFuncSetAttribute(bls_fused, cudaFuncAttributeMaxDynamicSharedMemorySize,
                             (int)sizeof(Smem));
        smem_set = 1;
    }
    bls_fused<<<N2V * CLUSTER, THREADS, sizeof(Smem)>>>(x, We, W0, Wp, bp, out);
}

// round 11
// speedup vs baseline: 16.2239x; 1.0099x over previous
#include <cuda_runtime.h>
#include <cstdint>

// Problem constants (from reference)
#define N1V   192
#define N2V   48
#define DINV  1024
#define DP1V  1025
#define DOUTV 512
#define LAMV  0.001f
#define LRV   0.01f
#define BETAD 0.02      // 2*LR (double)

// 48 clusters of 6 CTAs; each CTA owns 32 columns of its group's W.
// 512 threads: c8 = tid&7 -> float4 column group, r0 = tid>>3 -> row phase.
#define CLUSTER   6
#define COLS_CTA  32
#define THREADS   512
#define SDEPTH    5                      // sweep pipeline depth (per stream)
#define NSLOTS    10                     // total ring slots (epilogue uses all)
#define WSTRIDE   ((size_t)DP1V * N1V)   // 196800 floats per group matrix

struct __align__(16) Smem {
    float4 buf[NSLOTS][THREADS];         // 80KB ring: sweep We->0..4, W0->5..9
    float  h1s[1028];
    float  cpartA[64][33];
    float  cpartD[64][33];
    float  redA[16], redN[16], redH[16], predp[16];
    float  slotsA[8], slotsN[8];
    float  aS[32], dS[32], CsS[32];
    float  s100;
    double gam, bsig;
};

__device__ __forceinline__ float wred(float v) {
    v += __shfl_xor_sync(0xffffffffu, v, 16);
    v += __shfl_xor_sync(0xffffffffu, v, 8);
    v += __shfl_xor_sync(0xffffffffu, v, 4);
    v += __shfl_xor_sync(0xffffffffu, v, 2);
    v += __shfl_xor_sync(0xffffffffu, v, 1);
    return v;
}

// x^100 via repeated squaring: 100 = 64 + 32 + 4
__device__ __forceinline__ double pow100(double s) {
    double s2 = s * s, s4 = s2 * s2, s8 = s4 * s4;
    double s16 = s8 * s8, s32 = s16 * s16, s64 = s32 * s32;
    return s64 * s32 * s4;
}

__device__ __forceinline__ void cpasync16(void* sp, const void* gp) {
    uint32_t sa = (uint32_t)__cvta_generic_to_shared(sp);
    asm volatile("cp.async.cg.shared.global [%0], [%1], 16;"
                 :: "r"(sa), "l"(gp) : "memory");
}
#define CP_COMMIT() asm volatile("cp.async.commit_group;" ::: "memory")
#define CP_WAIT(n)  asm volatile("cp.async.wait_group %0;" :: "n"(n) : "memory")

__global__ void __launch_bounds__(THREADS, 2) __cluster_dims__(CLUSTER, 1, 1)
bls_fused(const float* __restrict__ x,
          const float* __restrict__ We,
          const float* __restrict__ W0,
          const float* __restrict__ Wp,
          const float* __restrict__ bp,
          float* __restrict__ out)     // [pred(512) | W_all]
{
    extern __shared__ Smem sm[];

    const int tid  = threadIdx.x;
    const int lane = tid & 31;
    const int wid  = tid >> 5;
    const int bid  = blockIdx.x;
    const int grp  = bid / CLUSTER;
    uint32_t rank;
    asm("mov.u32 %0, %%cluster_ctarank;" : "=r"(rank));
    const int col0 = (int)rank * COLS_CTA;
    const int c8   = tid & 7;            // float4 column-group 0..7
    const int r0   = tid >> 3;           // row phase 0..63

    const float* ebase = We + (size_t)grp * WSTRIDE + (size_t)(col0 + c8 * 4);
    const float* wbase = W0 + (size_t)grp * WSTRIDE + (size_t)(col0 + c8 * 4);

    // ---- Kick off the sweep pipeline FIRST: DRAM busy from cycle ~0.
    // Per-thread slots: thread t only ever touches buf[*][t], so the pipeline
    // needs cp.async.wait_group only, never __syncthreads.
    #pragma unroll
    for (int b = 0; b < SDEPTH; ++b) {
        const size_t off = (size_t)(r0 + (b << 6)) * N1V;
        cpasync16(&sm->buf[b][tid],          ebase + off);
        cpasync16(&sm->buf[SDEPTH + b][tid], wbase + off);
        CP_COMMIT();
    }

    // ---- h1 into smem; per-warp ||x||^2 partials; folded pred dot ----
    const float x0 = x[tid], x1 = x[tid + 512];
    sm->h1s[tid]       = x0;
    sm->h1s[tid + 512] = x1;
    if (tid == 0) sm->h1s[1024] = 1.0f;
    {
        float hq = wred(x0 * x0 + x1 * x1);
        if (lane == 0) sm->redH[wid] = hq;
    }
    // pred: CTAs 0..255 compute out[2*bid] (warps 0-7) and out[2*bid+1] (8-15)
    if (bid < 256) {
        const float* row = Wp + (size_t)(2 * bid + (wid >> 3)) * DINV
                              + (size_t)(wid & 7) * 128 + lane;
        float p = 0.0f;
        #pragma unroll
        for (int i = 0; i < 4; ++i)
            p = fmaf(row[i * 32], x[(wid & 7) * 128 + lane + i * 32], p);
        p = wred(p);
        if (lane == 0) sm->predp[wid] = p;
    }
    __syncthreads();
    if (bid < 256 && tid < 2) {
        float s = 0.0f;
        #pragma unroll
        for (int i = 0; i < 8; ++i) s += sm->predp[tid * 8 + i];
        out[2 * bid + tid] = s + bp[2 * bid + tid];
    }
    double h2 = 0.0;                     // only tid 0's value is ever used
    if (tid == 0) {
        double s = 1.0;                  // bias row contributes 1
        #pragma unroll
        for (int i = 0; i < 16; ++i) s += (double)sm->redH[i];
        h2 = s;
    }

    // ---- Fused pipelined sweep: A_k = h.We[:,k], d0_k = h.W0[:,k], ||W0||^2
    float4 accA = make_float4(0.f, 0.f, 0.f, 0.f);
    float4 accD = make_float4(0.f, 0.f, 0.f, 0.f);
    float  nrm  = 0.0f;
    #pragma unroll
    for (int k = 0; k < 16; ++k) {
        CP_WAIT(SDEPTH - 1);                    // batch k complete (in-order)
        const int sl = k % SDEPTH;              // compile-time after unroll
        float4 e = sm->buf[sl][tid];
        float4 w = sm->buf[SDEPTH + sl][tid];
        float  h = sm->h1s[r0 + (k << 6)];
        if (k + SDEPTH < 16) {                  // refill the slot just drained
            const size_t off = (size_t)(r0 + ((k + SDEPTH) << 6)) * N1V;
            cpasync16(&sm->buf[sl][tid],          ebase + off);
            cpasync16(&sm->buf[SDEPTH + sl][tid], wbase + off);
        }
        CP_COMMIT();                            // 1 group per k (may be empty)
        accA.x = fmaf(h, e.x, accA.x);  accA.y = fmaf(h, e.y, accA.y);
        accA.z = fmaf(h, e.z, accA.z);  accA.w = fmaf(h, e.w, accA.w);
        accD.x = fmaf(h, w.x, accD.x);  accD.y = fmaf(h, w.y, accD.y);
        accD.z = fmaf(h, w.z, accD.z);  accD.w = fmaf(h, w.w, accD.w);
        nrm = fmaf(w.x, w.x, nrm);  nrm = fmaf(w.y, w.y, nrm);
        nrm = fmaf(w.z, w.z, nrm);  nrm = fmaf(w.w, w.w, nrm);
    }
    if (tid < 8) {                       // bias row 1024 (h = 1)
        float4 e = *(const float4*)(ebase + (size_t)1024 * N1V);
        float4 w = *(const float4*)(wbase + (size_t)1024 * N1V);
        accA.x += e.x; accA.y += e.y; accA.z += e.z; accA.w += e.w;
        accD.x += w.x; accD.y += w.y; accD.z += w.z; accD.w += w.w;
        nrm = fmaf(w.x, w.x, nrm);  nrm = fmaf(w.y, w.y, nrm);
        nrm = fmaf(w.z, w.z, nrm);  nrm = fmaf(w.w, w.w, nrm);
    }

    // ---- Prefetch 10/16 epilogue W0 batches into the FULL ring NOW:
    // overlaps the reductions + cluster barrier + post-barrier latency.
    // Safe slot reuse: thread t already consumed all its sweep slots.
    #pragma unroll
    for (int b = 0; b < NSLOTS; ++b) {
        const size_t off = (size_t)(r0 + (b << 6)) * N1V;
        cpasync16(&sm->buf[b][tid], wbase + off);
        CP_COMMIT();
    }

    sm->cpartA[r0][c8 * 4 + 0] = accA.x;  sm->cpartA[r0][c8 * 4 + 1] = accA.y;
    sm->cpartA[r0][c8 * 4 + 2] = accA.z;  sm->cpartA[r0][c8 * 4 + 3] = accA.w;
    sm->cpartD[r0][c8 * 4 + 0] = accD.x;  sm->cpartD[r0][c8 * 4 + 1] = accD.y;
    sm->cpartD[r0][c8 * 4 + 2] = accD.z;  sm->cpartD[r0][c8 * 4 + 3] = accD.w;
    {
        float nw = wred(nrm);
        if (lane == 0) sm->redN[wid] = nw;
    }
    __syncthreads();

    // ---- Warp-parallel CTA column reduction: warp w owns columns 2w, 2w+1 ----
    {
        const int cA = 2 * wid, cB = 2 * wid + 1;
        float a0 = sm->cpartA[lane][cA] + sm->cpartA[lane + 32][cA];
        float a1 = sm->cpartA[lane][cB] + sm->cpartA[lane + 32][cB];
        float d0 = sm->cpartD[lane][cA] + sm->cpartD[lane + 32][cA];
        float d1 = sm->cpartD[lane][cB] + sm->cpartD[lane + 32][cB];
        a0 = wred(a0); a1 = wred(a1); d0 = wred(d0); d1 = wred(d1);
        if (lane == 0) {
            sm->aS[cA] = a0; sm->aS[cB] = a1;
            sm->dS[cA] = d0; sm->dS[cB] = d1;
            sm->redA[wid] = a0 * a0 + a1 * a1;
        }
    }
    __syncthreads();

    // ---- ONE combined cluster allreduce: {sum A^2, ||W0||^2} ----
    if (wid < 2) {
        float v = (lane < 16) ? (wid == 0 ? sm->redA[lane] : sm->redN[lane]) : 0.0f;
        v = wred(v);
        if (lane == 0) {
            float* slot = (wid == 0) ? &sm->slotsA[rank] : &sm->slotsN[rank];
            uint32_t la = (uint32_t)__cvta_generic_to_shared(slot);
            #pragma unroll
            for (int rk = 0; rk < CLUSTER; ++rk) {
                uint32_t ra;
                asm volatile("mapa.shared::cluster.u32 %0, %1, %2;"
                             : "=r"(ra) : "r"(la), "r"((uint32_t)rk));
                asm volatile("st.shared::cluster.f32 [%0], %1;"
                             :: "r"(ra), "f"(v) : "memory");
            }
        }
    }
    asm volatile("barrier.cluster.arrive.aligned;" ::: "memory");
    asm volatile("barrier.cluster.wait.aligned;"   ::: "memory");

    // ---- Closed form of 100 GD steps with frozen s = 1 - LR*LAM/||W0|| ----
    // w100 = s^100 w0 + [gam*d0 + beta*sig*(A/||A||)] h
    if (tid == 0) {
        float at = 0.0f, nt = 0.0f;
        #pragma unroll
        for (int rk = 0; rk < CLUSTER; ++rk) { at += sm->slotsA[rk]; nt += sm->slotsN[rk]; }
        double s     = 1.0 - (double)LRV * (double)LAMV / sqrt((double)nt);
        double mu    = s - BETAD * h2;
        double s100  = pow100(s);
        double mu100 = pow100(mu);
        sm->gam  = (mu100 - s100) / h2;
        sm->bsig = BETAD * (1.0 - mu100) / (1.0 - mu) / sqrt((double)at);
        sm->s100 = (float)s100;
    }
    __syncthreads();
    if (tid < 32)
        sm->CsS[tid] = (float)(sm->gam * (double)sm->dS[tid]
                             + sm->bsig * (double)sm->aS[tid]);
    __syncthreads();

    // ---- Pipelined epilogue: w_out = s100*w0 + C_k*h; streaming stores.
    // Batches 0..9 were staged pre-barrier; 10..15 refill from L2 in-loop.
    const float s100f = sm->s100;
    const float4 Cv = make_float4(sm->CsS[c8 * 4 + 0], sm->CsS[c8 * 4 + 1],
                                  sm->CsS[c8 * 4 + 2], sm->CsS[c8 * 4 + 3]);
    float* obase = out + DOUTV + (size_t)grp * WSTRIDE + (size_t)(col0 + c8 * 4);
    #pragma unroll
    for (int k = 0; k < 16; ++k) {
        CP_WAIT(NSLOTS - 1);                    // batch k complete
        const int sl = k % NSLOTS;              // compile-time after unroll
        float4 v = sm->buf[sl][tid];
        if (k + NSLOTS < 16) {                  // refill slot just freed
            const size_t off = (size_t)(r0 + ((k + NSLOTS) << 6)) * N1V;
            cpasync16(&sm->buf[sl][tid], wbase + off);
        }
        CP_COMMIT();
        const float h = sm->h1s[r0 + (k << 6)];
        float4 o;
        o.x = fmaf(s100f, v.x, h * Cv.x);
        o.y = fmaf(s100f, v.y, h * Cv.y);
        o.z = fmaf(s100f, v.z, h * Cv.z);
        o.w = fmaf(s100f, v.w, h * Cv.w);
        __stcs((float4*)(obase + (size_t)(r0 + (k << 6)) * N1V), o);
    }
    if (tid < 8) {                               // bias row (h = 1)
        float4 v = *(const float4*)(wbase + (size_t)1024 * N1V);
        float4 o;
        o.x = fmaf(s100f, v.x, Cv.x);
        o.y = fmaf(s100f, v.y, Cv.y);
        o.z = fmaf(s100f, v.z, Cv.z);
        o.w = fmaf(s100f, v.w, Cv.w);
        __stcs((float4*)(obase + (size_t)1024 * N1V), o);
    }
    // No trailing cluster sync needed: remote DSMEM slot stores were published
    // by the allreduce barrier; peers only read their own smem afterwards.
}

extern "C" void kernel_launch(void* const* d_in, const int* in_sizes, int n_in,
                              void* d_out, int out_size)
{
    (void)in_sizes; (void)n_in; (void)out_size;
    const float* x  = (const float*)d_in[0];   // (1024,)
    const float* We = (const float*)d_in[1];   // (48, 1025, 192)
    const float* W0 = (const float*)d_in[2];   // (48, 1025, 192)
    const float* Wp = (const float*)d_in[3];   // (512, 1024)
    const float* bp = (const float*)d_in[4];   // (512,)
    float* out = (float*)d_out;                // [pred(512) | W_all]

    static int smem_set = 0;
    if (!smem_set) {
        cudaFuncSetAttribute(bls_fused, cudaFuncAttributeMaxDynamicSharedMemorySize,
                             (int)sizeof(Smem));
        smem_set = 1;
    }
    bls_fused<<<N2V * CLUSTER, THREADS, sizeof(Smem)>>>(x, We, W0, Wp, bp, out);
}